// round 8
// baseline (speedup 1.0000x reference)
#include <cuda_runtime.h>
#include <cstddef>
#include <cstdint>

// Problem constants (fixed by setup_inputs)
#define BATCH 1024
#define F1 10          // layer-1 fanout
#define F0 25          // layer-0 fanout
#define D 128          // feature dim
#define NROWS1 (BATCH*F1)        // 10240
#define NTOT (BATCH + NROWS1)    // 11264
#define RT 32                    // rows per layer-0 block (NTOT/RT = 352)

// Scratch (device globals — no allocations allowed).
__device__ float g_N[(size_t)NTOT * 256];

// ---------------------------------------------------------------------------
// cp.async helpers (LDGSTS: no destination registers -> latency hiding does
// not depend on register-file MLP)
// ---------------------------------------------------------------------------
__device__ __forceinline__ void cp16(void* dst, const void* src) {
    uint32_t d = (uint32_t)__cvta_generic_to_shared(dst);
    asm volatile("cp.async.ca.shared.global [%0], [%1], 16;" :: "r"(d), "l"(src));
}
__device__ __forceinline__ void cp_commit() {
    asm volatile("cp.async.commit_group;");
}
template<int N>
__device__ __forceinline__ void cp_wait() {
    asm volatile("cp.async.wait_group %0;" :: "n"(N));
}

// ---------------------------------------------------------------------------
// Gather: warp-cooperative. Each warp produces self row + neighbor-mean row
// for rows warp, warp+8, warp+16, warp+24. Self index computed inline
// (redundantly per lane; broadcast loads) -> no smem, no barrier needed.
// ---------------------------------------------------------------------------
template<int CNT, bool LVL0>
__device__ __forceinline__ void gather_rows(
    const float* __restrict__ features, const int* __restrict__ adj,
    const int* __restrict__ batch, int r0,
    float (*Xs)[D], float (*Xn)[D], int warp, int lane)
{
    #pragma unroll
    for (int rr = warp; rr < RT; rr += 8) {
        int r = r0 + rr;
        int s;
        if (LVL0) {
            s = __ldg(batch + r);
        } else {
            int i = r - BATCH;
            s = __ldg(adj + (size_t)__ldg(batch + i / F1) * 128 + (i % F1));
        }
        ((float4*)Xs[rr])[lane] =
            ((const float4*)(features + (size_t)s * D))[lane];

        const int* arow = adj + (size_t)s * 128;
        float4 acc = make_float4(0.f, 0.f, 0.f, 0.f);
        #pragma unroll
        for (int j = 0; j < CNT; j++) {
            int nb = __ldg(arow + j);
            float4 nv = ((const float4*)(features + (size_t)nb * D))[lane];
            acc.x += nv.x; acc.y += nv.y; acc.z += nv.z; acc.w += nv.w;
        }
        const float inv = 1.f / CNT;
        acc.x *= inv; acc.y *= inv; acc.z *= inv; acc.w *= inv;
        ((float4*)Xn[rr])[lane] = acc;
    }
}

// ---------------------------------------------------------------------------
// K_A: fused sample + aggregate + layer-0 GEMM (+ReLU).
// grid = 352 x 256 thr; block = 32 rows x 256 cols. K=128 in 16 chunks of 8,
// double-buffered smem weights via cp.async (prefetched before gather).
// Static smem = 16+16+16 = 48 KB exactly.
// ---------------------------------------------------------------------------
__global__ void __launch_bounds__(256, 3)
k_layer0(const float* __restrict__ features, const int* __restrict__ adj,
         const int* __restrict__ batch,
         const float* __restrict__ ws0, const float* __restrict__ wn0)
{
    __shared__ float Xs[RT][D];        // 16 KB self rows
    __shared__ float Xn[RT][D];        // 16 KB neighbor means
    __shared__ float Wb[2][8][256];    // 16 KB double-buffered W chunk

    const int tid  = threadIdx.x;
    const int warp = tid >> 5, lane = tid & 31;
    const int r0   = blockIdx.x * RT;

    // Cooperative W-chunk prefetch: chunk c = k rows [8c, 8c+8) of the
    // 256-wide combined weight [ws0 | wn0]. 2 cp.async x 16B per thread.
    auto pref = [&](int c, int buf) {
        #pragma unroll
        for (int j = 0; j < 2; j++) {
            int idx  = tid + j * 256;          // 0..511 -> 8x256 floats /4
            int kk   = idx >> 6;               // 0..7
            int rest = idx & 63;
            int half = rest >> 5, quad = rest & 31;
            const float* src =
                (half ? wn0 : ws0) + (size_t)(c * 8 + kk) * 128 + quad * 4;
            cp16(&Wb[buf][kk][half * 128 + quad * 4], src);
        }
        cp_commit();
    };
    pref(0, 0);
    pref(1, 1);

    // Gather (overlaps with the in-flight weight prefetches)
    if (r0 < BATCH)
        gather_rows<F1, true >(features, adj, batch, r0, Xs, Xn, warp, lane);
    else
        gather_rows<F0, false>(features, adj, batch, r0, Xs, Xn, warp, lane);

    // GEMM: thread owns output column tid for all 32 rows.
    float acc[RT];
    #pragma unroll
    for (int r = 0; r < RT; r++) acc[r] = 0.f;

    const float4* X4 = (const float4*)((tid < 128) ? &Xs[0][0] : &Xn[0][0]);

    #pragma unroll
    for (int c = 0; c < 16; c++) {
        if (c < 15) cp_wait<1>(); else cp_wait<0>();
        __syncthreads();                       // chunk visible (+ gather on c=0)
        const int buf = c & 1;
        #pragma unroll
        for (int kq = 0; kq < 2; kq++) {
            float w0 = Wb[buf][kq * 4 + 0][tid];
            float w1 = Wb[buf][kq * 4 + 1][tid];
            float w2 = Wb[buf][kq * 4 + 2][tid];
            float w3 = Wb[buf][kq * 4 + 3][tid];
            #pragma unroll
            for (int r = 0; r < RT; r++) {
                float4 xv = X4[r * (D / 4) + c * 2 + kq];   // broadcast LDS
                float a = acc[r];
                a = fmaf(xv.x, w0, a);
                a = fmaf(xv.y, w1, a);
                a = fmaf(xv.z, w2, a);
                a = fmaf(xv.w, w3, a);
                acc[r] = a;
            }
        }
        __syncthreads();                       // buffer free
        if (c + 2 < 16) pref(c + 2, buf);      // refill the buffer just freed
    }

    #pragma unroll
    for (int r = 0; r < RT; r++)
        g_N[(size_t)(r0 + r) * 256 + tid] = fmaxf(acc[r], 0.f);
}

// ---------------------------------------------------------------------------
// K_B: fused tail: mean-of-10 + layer-1 GEMM + l2-normalize + pred.
// grid = 256 x 256 thr; 4 batch rows per block. K=256 in 16 chunks of 16,
// double-buffered cp.async weights. Static smem = 12 + 32 = 44 KB.
// ---------------------------------------------------------------------------
__global__ void __launch_bounds__(256)
k_tail(const float* __restrict__ ws1, const float* __restrict__ wn1,
       const float* __restrict__ wp, float* __restrict__ out)
{
    __shared__ float Ns[4][256];        // n0 rows
    __shared__ float Ms[4][256];        // m1 rows
    __shared__ float Ys[4][256];        // layer-1 outputs
    __shared__ float Wb[2][16][256];    // 32 KB double-buffered W chunk
    __shared__ float inv4[4];

    const int tid = threadIdx.x;
    const int r0  = blockIdx.x * 4;

    auto pref = [&](int c, int buf) {
        #pragma unroll
        for (int j = 0; j < 4; j++) {
            int idx  = tid + j * 256;          // 0..1023 -> 16x256 floats /4
            int kk   = idx >> 6;               // 0..15
            int rest = idx & 63;
            int half = rest >> 5, quad = rest & 31;
            const float* src =
                (half ? wn1 : ws1) + (size_t)(c * 16 + kk) * 128 + quad * 4;
            cp16(&Wb[buf][kk][half * 128 + quad * 4], src);
        }
        cp_commit();
    };
    pref(0, 0);
    pref(1, 1);

    // n0 rows + mean-of-10 rows (overlaps with weight prefetch)
    #pragma unroll
    for (int rr = 0; rr < 4; rr++)
        Ns[rr][tid] = g_N[(size_t)(r0 + rr) * 256 + tid];
    #pragma unroll
    for (int rr = 0; rr < 4; rr++) {
        const float* base = g_N + (size_t)(BATCH + (r0 + rr) * F1) * 256 + tid;
        float s = 0.f;
        #pragma unroll
        for (int j = 0; j < F1; j++)
            s += base[(size_t)j * 256];
        Ms[rr][tid] = s * (1.f / F1);
    }

    // Layer-1 GEMM: thread owns col tid for 4 rows.
    float acc[4] = {0.f, 0.f, 0.f, 0.f};
    const float4* X4 = (const float4*)((tid < 128) ? &Ns[0][0] : &Ms[0][0]);

    #pragma unroll
    for (int c = 0; c < 16; c++) {
        if (c < 15) cp_wait<1>(); else cp_wait<0>();
        __syncthreads();
        const int buf = c & 1;
        #pragma unroll
        for (int kq = 0; kq < 4; kq++) {
            float w0 = Wb[buf][kq * 4 + 0][tid];
            float w1 = Wb[buf][kq * 4 + 1][tid];
            float w2 = Wb[buf][kq * 4 + 2][tid];
            float w3 = Wb[buf][kq * 4 + 3][tid];
            #pragma unroll
            for (int r = 0; r < 4; r++) {
                float4 xv = X4[r * 64 + c * 4 + kq];
                float a = acc[r];
                a = fmaf(xv.x, w0, a);
                a = fmaf(xv.y, w1, a);
                a = fmaf(xv.z, w2, a);
                a = fmaf(xv.w, w3, a);
                acc[r] = a;
            }
        }
        __syncthreads();
        if (c + 2 < 16) pref(c + 2, buf);
    }

    #pragma unroll
    for (int r = 0; r < 4; r++)
        Ys[r][tid] = acc[r];
    __syncthreads();

    // Per-row inverse L2 norm: warp w (0..3) reduces row w
    const int warp = tid >> 5, lane = tid & 31;
    if (warp < 4) {
        float s = 0.f;
        #pragma unroll
        for (int k = lane; k < 256; k += 32) {
            float v = Ys[warp][k];
            s += v * v;
        }
        #pragma unroll
        for (int o = 16; o > 0; o >>= 1)
            s += __shfl_xor_sync(0xFFFFFFFFu, s, o);
        if (lane == 0)
            inv4[warp] = rsqrtf(fmaxf(s, 1e-12f));
    }
    __syncthreads();

    // Pred head [256 -> 50]; normalization folded as output scale.
    const int c  = tid & 63;
    const int rg = tid >> 6;
    if (c < 50) {
        float a = 0.f;
        #pragma unroll 16
        for (int k = 0; k < 256; k++)
            a = fmaf(Ys[rg][k], __ldg(wp + (size_t)k * 50 + c), a);
        out[(size_t)(r0 + rg) * 50 + c] = a * inv4[rg];
    }
}

// ---------------------------------------------------------------------------
extern "C" void kernel_launch(void* const* d_in, const int* in_sizes, int n_in,
                              void* d_out, int out_size)
{
    const float* features = (const float*)d_in[0];
    const int*   adj      = (const int*)d_in[1];
    const int*   batch    = (const int*)d_in[2];   // int32 (JAX x64 disabled)
    const float* ws0      = (const float*)d_in[3];
    const float* wn0      = (const float*)d_in[4];
    const float* ws1      = (const float*)d_in[5];
    const float* wn1      = (const float*)d_in[6];
    const float* wp       = (const float*)d_in[7];
    float*       out      = (float*)d_out;

    k_layer0<<<NTOT / RT, 256>>>(features, adj, batch, ws0, wn0);
    k_tail<<<BATCH / 4, 256>>>(ws1, wn1, wp, out);
}

// round 11
// speedup vs baseline: 1.0012x; 1.0012x over previous
#include <cuda_runtime.h>
#include <cstddef>
#include <cstdint>

// Problem constants (fixed by setup_inputs)
#define BATCH 1024
#define F1 10          // layer-1 fanout
#define F0 25          // layer-0 fanout
#define D 128          // feature dim
#define NROWS1 (BATCH*F1)        // 10240
#define NTOT (BATCH + NROWS1)    // 11264
#define RT 32                    // rows per layer-0 block (NTOT/RT = 352)

// Scratch (device globals — no allocations allowed).
__device__ float g_N[(size_t)NTOT * 256];

// ---------------------------------------------------------------------------
// cp.async helpers (LDGSTS: no destination registers -> weight streaming does
// not consume the register budget the gather needs for MLP)
// ---------------------------------------------------------------------------
__device__ __forceinline__ void cp16(void* dst, const void* src) {
    uint32_t d = (uint32_t)__cvta_generic_to_shared(dst);
    asm volatile("cp.async.ca.shared.global [%0], [%1], 16;" :: "r"(d), "l"(src));
}
__device__ __forceinline__ void cp_commit() {
    asm volatile("cp.async.commit_group;");
}
template<int N>
__device__ __forceinline__ void cp_wait() {
    asm volatile("cp.async.wait_group %0;" :: "n"(N));
}

// ---------------------------------------------------------------------------
// Gather: warp-cooperative. Each warp produces self row + neighbor-mean row
// for rows warp, warp+8, warp+16, warp+24. Self index resolved inline
// (redundant across lanes -> broadcast loads; no smem, no barrier).
// CNT compile-time -> fully unrolled j-loop -> high MLP (no reg cap!).
// ---------------------------------------------------------------------------
template<int CNT, bool LVL0>
__device__ __forceinline__ void gather_rows(
    const float* __restrict__ features, const int* __restrict__ adj,
    const int* __restrict__ batch, int r0,
    float (*Xs)[D], float (*Xn)[D], int warp, int lane)
{
    #pragma unroll
    for (int rr = warp; rr < RT; rr += 8) {
        int r = r0 + rr;
        int s;
        if (LVL0) {
            s = __ldg(batch + r);
        } else {
            int i = r - BATCH;
            s = __ldg(adj + (size_t)__ldg(batch + i / F1) * 128 + (i % F1));
        }
        ((float4*)Xs[rr])[lane] =
            ((const float4*)(features + (size_t)s * D))[lane];

        const int* arow = adj + (size_t)s * 128;
        float4 acc = make_float4(0.f, 0.f, 0.f, 0.f);
        #pragma unroll
        for (int j = 0; j < CNT; j++) {
            int nb = __ldg(arow + j);
            float4 nv = ((const float4*)(features + (size_t)nb * D))[lane];
            acc.x += nv.x; acc.y += nv.y; acc.z += nv.z; acc.w += nv.w;
        }
        const float inv = 1.f / CNT;
        acc.x *= inv; acc.y *= inv; acc.z *= inv; acc.w *= inv;
        ((float4*)Xn[rr])[lane] = acc;
    }
}

// ---------------------------------------------------------------------------
// K_A: fused sample + aggregate + layer-0 GEMM (+ReLU).
// grid = 352 x 256 thr; block = 32 rows x 256 cols. K=128 in 16 chunks of 8,
// double-buffered smem weights via cp.async (prefetched before gather).
// Static smem = 16+16+16 = 48 KB exactly. NO register cap.
// (Resubmission of round-9 kernel: prior run died to a container-level infra
//  failure with no compile/runtime diagnostic.)
// ---------------------------------------------------------------------------
__global__ void __launch_bounds__(256)
k_layer0(const float* __restrict__ features, const int* __restrict__ adj,
         const int* __restrict__ batch,
         const float* __restrict__ ws0, const float* __restrict__ wn0)
{
    __shared__ float Xs[RT][D];        // 16 KB self rows
    __shared__ float Xn[RT][D];        // 16 KB neighbor means
    __shared__ float Wb[2][8][256];    // 16 KB double-buffered W chunk

    const int tid  = threadIdx.x;
    const int warp = tid >> 5, lane = tid & 31;
    const int r0   = blockIdx.x * RT;

    // Cooperative W-chunk prefetch: chunk c = k rows [8c, 8c+8) of the
    // 256-wide combined weight [ws0 | wn0]. 2 cp.async x 16B per thread.
    auto pref = [&](int c, int buf) {
        #pragma unroll
        for (int j = 0; j < 2; j++) {
            int idx  = tid + j * 256;          // 0..511 -> 8x256 floats /4
            int kk   = idx >> 6;               // 0..7
            int rest = idx & 63;
            int half = rest >> 5, quad = rest & 31;
            const float* src =
                (half ? wn0 : ws0) + (size_t)(c * 8 + kk) * 128 + quad * 4;
            cp16(&Wb[buf][kk][half * 128 + quad * 4], src);
        }
        cp_commit();
    };
    pref(0, 0);
    pref(1, 1);

    // Gather (overlaps with the in-flight weight prefetches)
    if (r0 < BATCH)
        gather_rows<F1, true >(features, adj, batch, r0, Xs, Xn, warp, lane);
    else
        gather_rows<F0, false>(features, adj, batch, r0, Xs, Xn, warp, lane);

    // GEMM: thread owns output column tid for all 32 rows.
    float acc[RT];
    #pragma unroll
    for (int r = 0; r < RT; r++) acc[r] = 0.f;

    const float4* X4 = (const float4*)((tid < 128) ? &Xs[0][0] : &Xn[0][0]);

    #pragma unroll
    for (int c = 0; c < 16; c++) {
        if (c < 15) cp_wait<1>(); else cp_wait<0>();
        __syncthreads();                       // chunk visible (+ gather on c=0)
        const int buf = c & 1;
        #pragma unroll
        for (int kq = 0; kq < 2; kq++) {
            float w0 = Wb[buf][kq * 4 + 0][tid];
            float w1 = Wb[buf][kq * 4 + 1][tid];
            float w2 = Wb[buf][kq * 4 + 2][tid];
            float w3 = Wb[buf][kq * 4 + 3][tid];
            #pragma unroll
            for (int r = 0; r < RT; r++) {
                float4 xv = X4[r * (D / 4) + c * 2 + kq];   // broadcast LDS
                float a = acc[r];
                a = fmaf(xv.x, w0, a);
                a = fmaf(xv.y, w1, a);
                a = fmaf(xv.z, w2, a);
                a = fmaf(xv.w, w3, a);
                acc[r] = a;
            }
        }
        __syncthreads();                       // buffer free
        if (c + 2 < 16) pref(c + 2, buf);      // refill the buffer just freed
    }

    #pragma unroll
    for (int r = 0; r < RT; r++)
        g_N[(size_t)(r0 + r) * 256 + tid] = fmaxf(acc[r], 0.f);
}

// ---------------------------------------------------------------------------
// K_B: fused tail: mean-of-10 + layer-1 GEMM + l2-normalize + pred.
// (unchanged from round 8: measured 33 us)
// ---------------------------------------------------------------------------
__global__ void __launch_bounds__(256)
k_tail(const float* __restrict__ ws1, const float* __restrict__ wn1,
       const float* __restrict__ wp, float* __restrict__ out)
{
    __shared__ float Ns[4][256];        // n0 rows
    __shared__ float Ms[4][256];        // m1 rows
    __shared__ float Ys[4][256];        // layer-1 outputs
    __shared__ float Wb[2][16][256];    // 32 KB double-buffered W chunk
    __shared__ float inv4[4];

    const int tid = threadIdx.x;
    const int r0  = blockIdx.x * 4;

    auto pref = [&](int c, int buf) {
        #pragma unroll
        for (int j = 0; j < 4; j++) {
            int idx  = tid + j * 256;          // 0..1023 -> 16x256 floats /4
            int kk   = idx >> 6;               // 0..15
            int rest = idx & 63;
            int half = rest >> 5, quad = rest & 31;
            const float* src =
                (half ? wn1 : ws1) + (size_t)(c * 16 + kk) * 128 + quad * 4;
            cp16(&Wb[buf][kk][half * 128 + quad * 4], src);
        }
        cp_commit();
    };
    pref(0, 0);
    pref(1, 1);

    // n0 rows + mean-of-10 rows (overlaps with weight prefetch)
    #pragma unroll
    for (int rr = 0; rr < 4; rr++)
        Ns[rr][tid] = g_N[(size_t)(r0 + rr) * 256 + tid];
    #pragma unroll
    for (int rr = 0; rr < 4; rr++) {
        const float* base = g_N + (size_t)(BATCH + (r0 + rr) * F1) * 256 + tid;
        float s = 0.f;
        #pragma unroll
        for (int j = 0; j < F1; j++)
            s += base[(size_t)j * 256];
        Ms[rr][tid] = s * (1.f / F1);
    }

    // Layer-1 GEMM: thread owns col tid for 4 rows.
    float acc[4] = {0.f, 0.f, 0.f, 0.f};
    const float4* X4 = (const float4*)((tid < 128) ? &Ns[0][0] : &Ms[0][0]);

    #pragma unroll
    for (int c = 0; c < 16; c++) {
        if (c < 15) cp_wait<1>(); else cp_wait<0>();
        __syncthreads();
        const int buf = c & 1;
        #pragma unroll
        for (int kq = 0; kq < 4; kq++) {
            float w0 = Wb[buf][kq * 4 + 0][tid];
            float w1 = Wb[buf][kq * 4 + 1][tid];
            float w2 = Wb[buf][kq * 4 + 2][tid];
            float w3 = Wb[buf][kq * 4 + 3][tid];
            #pragma unroll
            for (int r = 0; r < 4; r++) {
                float4 xv = X4[r * 64 + c * 4 + kq];
                float a = acc[r];
                a = fmaf(xv.x, w0, a);
                a = fmaf(xv.y, w1, a);
                a = fmaf(xv.z, w2, a);
                a = fmaf(xv.w, w3, a);
                acc[r] = a;
            }
        }
        __syncthreads();
        if (c + 2 < 16) pref(c + 2, buf);
    }

    #pragma unroll
    for (int r = 0; r < 4; r++)
        Ys[r][tid] = acc[r];
    __syncthreads();

    // Per-row inverse L2 norm: warp w (0..3) reduces row w
    const int warp = tid >> 5, lane = tid & 31;
    if (warp < 4) {
        float s = 0.f;
        #pragma unroll
        for (int k = lane; k < 256; k += 32) {
            float v = Ys[warp][k];
            s += v * v;
        }
        #pragma unroll
        for (int o = 16; o > 0; o >>= 1)
            s += __shfl_xor_sync(0xFFFFFFFFu, s, o);
        if (lane == 0)
            inv4[warp] = rsqrtf(fmaxf(s, 1e-12f));
    }
    __syncthreads();

    // Pred head [256 -> 50]; normalization folded as output scale.
    const int c  = tid & 63;
    const int rg = tid >> 6;
    if (c < 50) {
        float a = 0.f;
        #pragma unroll 16
        for (int k = 0; k < 256; k++)
            a = fmaf(Ys[rg][k], __ldg(wp + (size_t)k * 50 + c), a);
        out[(size_t)(r0 + rg) * 50 + c] = a * inv4[rg];
    }
}

// ---------------------------------------------------------------------------
extern "C" void kernel_launch(void* const* d_in, const int* in_sizes, int n_in,
                              void* d_out, int out_size)
{
    const float* features = (const float*)d_in[0];
    const int*   adj      = (const int*)d_in[1];
    const int*   batch    = (const int*)d_in[2];   // int32 (JAX x64 disabled)
    const float* ws0      = (const float*)d_in[3];
    const float* wn0      = (const float*)d_in[4];
    const float* ws1      = (const float*)d_in[5];
    const float* wn1      = (const float*)d_in[6];
    const float* wp       = (const float*)d_in[7];
    float*       out      = (float*)d_out;

    k_layer0<<<NTOT / RT, 256>>>(features, adj, batch, ws0, wn0);
    k_tail<<<BATCH / 4, 256>>>(ws1, wn1, wp, out);
}

// round 12
// speedup vs baseline: 1.2073x; 1.2058x over previous
#include <cuda_runtime.h>
#include <cstddef>
#include <cstdint>

// Problem constants (fixed by setup_inputs)
#define BATCH 1024
#define F1 10          // layer-1 fanout
#define F0 25          // layer-0 fanout
#define D 128          // feature dim
#define NROWS1 (BATCH*F1)        // 10240
#define NTOT (BATCH + NROWS1)    // 11264
#define RT 16                    // rows per layer-0 block (NTOT/RT = 704)

// Scratch (device globals — no allocations allowed).
__device__ float g_N[(size_t)NTOT * 256];

// ---------------------------------------------------------------------------
// cp.async helpers (used by k_tail only)
// ---------------------------------------------------------------------------
__device__ __forceinline__ void cp16(void* dst, const void* src) {
    uint32_t d = (uint32_t)__cvta_generic_to_shared(dst);
    asm volatile("cp.async.ca.shared.global [%0], [%1], 16;" :: "r"(d), "l"(src));
}
__device__ __forceinline__ void cp_commit() {
    asm volatile("cp.async.commit_group;");
}
template<int N>
__device__ __forceinline__ void cp_wait() {
    asm volatile("cp.async.wait_group %0;" :: "n"(N));
}

// ---------------------------------------------------------------------------
// Gather: warp-cooperative. Warp w produces self row + neighbor-mean row for
// rows w and w+8 of the 16-row tile. Self index resolved inline (lane-uniform
// -> broadcast loads). CNT compile-time -> fully unrolled -> high MLP.
// ---------------------------------------------------------------------------
template<int CNT, bool LVL0>
__device__ __forceinline__ void gather_rows(
    const float* __restrict__ features, const int* __restrict__ adj,
    const int* __restrict__ batch, int r0,
    float (*Xs)[D], float (*Xn)[D], int warp, int lane)
{
    #pragma unroll
    for (int rr = warp; rr < RT; rr += 8) {
        int r = r0 + rr;
        int s;
        if (LVL0) {
            s = __ldg(batch + r);
        } else {
            int i = r - BATCH;
            s = __ldg(adj + (size_t)__ldg(batch + i / F1) * 128 + (i % F1));
        }
        ((float4*)Xs[rr])[lane] =
            ((const float4*)(features + (size_t)s * D))[lane];

        const int* arow = adj + (size_t)s * 128;
        float4 acc = make_float4(0.f, 0.f, 0.f, 0.f);
        #pragma unroll
        for (int j = 0; j < CNT; j++) {
            int nb = __ldg(arow + j);
            float4 nv = ((const float4*)(features + (size_t)nb * D))[lane];
            acc.x += nv.x; acc.y += nv.y; acc.z += nv.z; acc.w += nv.w;
        }
        const float inv = 1.f / CNT;
        acc.x *= inv; acc.y *= inv; acc.z *= inv; acc.w *= inv;
        ((float4*)Xn[rr])[lane] = acc;
    }
}

// ---------------------------------------------------------------------------
// K_A: fused sample + aggregate + layer-0 GEMM (+ReLU).
// grid = 704 x 256 thr; block = 16 rows x 256 cols. smem = 16 KB only ->
// 4+ blocks/SM so gather (latency-bound) and GEMM (FFMA-bound) phases of
// different blocks overlap. Weights streamed per-thread from L2 with a
// register double-buffer (w[2][8]) -> no block-wide barriers in the k-loop.
// ---------------------------------------------------------------------------
__global__ void __launch_bounds__(256)
k_layer0(const float* __restrict__ features, const int* __restrict__ adj,
         const int* __restrict__ batch,
         const float* __restrict__ ws0, const float* __restrict__ wn0)
{
    __shared__ float Xs[RT][D];        // 8 KB self rows
    __shared__ float Xn[RT][D];        // 8 KB neighbor means

    const int tid  = threadIdx.x;
    const int warp = tid >> 5, lane = tid & 31;
    const int r0   = blockIdx.x * RT;

    // Gather phase
    if (r0 < BATCH)
        gather_rows<F1, true >(features, adj, batch, r0, Xs, Xn, warp, lane);
    else
        gather_rows<F0, false>(features, adj, batch, r0, Xs, Xn, warp, lane);
    __syncthreads();

    // GEMM: thread owns output column tid for all 16 rows.
    // cols [0,128): relu(Xs @ ws0); cols [128,256): relu(Xn @ wn0)
    float acc[RT];
    #pragma unroll
    for (int r = 0; r < RT; r++) acc[r] = 0.f;

    const float4* X4   = (const float4*)((tid < 128) ? &Xs[0][0] : &Xn[0][0]);
    const float*  wcol = ((tid < 128) ? ws0 : wn0) + (tid & 127);

    // Software-pipelined weight groups: load group k8+1 while computing k8.
    float w[2][8];
    #pragma unroll
    for (int j = 0; j < 8; j++)
        w[0][j] = __ldg(wcol + (size_t)j * 128);

    #pragma unroll
    for (int k8 = 0; k8 < D / 8; k8++) {
        const int cur = k8 & 1, nxt = cur ^ 1;
        if (k8 + 1 < D / 8) {
            #pragma unroll
            for (int j = 0; j < 8; j++)
                w[nxt][j] = __ldg(wcol + (size_t)((k8 + 1) * 8 + j) * 128);
        }
        #pragma unroll
        for (int h = 0; h < 2; h++) {
            #pragma unroll
            for (int r = 0; r < RT; r++) {
                float4 xv = X4[r * (D / 4) + k8 * 2 + h];   // broadcast LDS
                float a = acc[r];
                a = fmaf(xv.x, w[cur][h * 4 + 0], a);
                a = fmaf(xv.y, w[cur][h * 4 + 1], a);
                a = fmaf(xv.z, w[cur][h * 4 + 2], a);
                a = fmaf(xv.w, w[cur][h * 4 + 3], a);
                acc[r] = a;
            }
        }
    }

    #pragma unroll
    for (int r = 0; r < RT; r++)
        g_N[(size_t)(r0 + r) * 256 + tid] = fmaxf(acc[r], 0.f);
}

// ---------------------------------------------------------------------------
// K_B: fused tail: mean-of-10 + layer-1 GEMM + l2-normalize + pred.
// (unchanged from round 8: measured 33 us twice)
// ---------------------------------------------------------------------------
__global__ void __launch_bounds__(256)
k_tail(const float* __restrict__ ws1, const float* __restrict__ wn1,
       const float* __restrict__ wp, float* __restrict__ out)
{
    __shared__ float Ns[4][256];        // n0 rows
    __shared__ float Ms[4][256];        // m1 rows
    __shared__ float Ys[4][256];        // layer-1 outputs
    __shared__ float Wb[2][16][256];    // 32 KB double-buffered W chunk
    __shared__ float inv4[4];

    const int tid = threadIdx.x;
    const int r0  = blockIdx.x * 4;

    auto pref = [&](int c, int buf) {
        #pragma unroll
        for (int j = 0; j < 4; j++) {
            int idx  = tid + j * 256;          // 0..1023 -> 16x256 floats /4
            int kk   = idx >> 6;               // 0..15
            int rest = idx & 63;
            int half = rest >> 5, quad = rest & 31;
            const float* src =
                (half ? wn1 : ws1) + (size_t)(c * 16 + kk) * 128 + quad * 4;
            cp16(&Wb[buf][kk][half * 128 + quad * 4], src);
        }
        cp_commit();
    };
    pref(0, 0);
    pref(1, 1);

    // n0 rows + mean-of-10 rows (overlaps with weight prefetch)
    #pragma unroll
    for (int rr = 0; rr < 4; rr++)
        Ns[rr][tid] = g_N[(size_t)(r0 + rr) * 256 + tid];
    #pragma unroll
    for (int rr = 0; rr < 4; rr++) {
        const float* base = g_N + (size_t)(BATCH + (r0 + rr) * F1) * 256 + tid;
        float s = 0.f;
        #pragma unroll
        for (int j = 0; j < F1; j++)
            s += base[(size_t)j * 256];
        Ms[rr][tid] = s * (1.f / F1);
    }

    // Layer-1 GEMM: thread owns col tid for 4 rows.
    float acc[4] = {0.f, 0.f, 0.f, 0.f};
    const float4* X4 = (const float4*)((tid < 128) ? &Ns[0][0] : &Ms[0][0]);

    #pragma unroll
    for (int c = 0; c < 16; c++) {
        if (c < 15) cp_wait<1>(); else cp_wait<0>();
        __syncthreads();
        const int buf = c & 1;
        #pragma unroll
        for (int kq = 0; kq < 4; kq++) {
            float w0 = Wb[buf][kq * 4 + 0][tid];
            float w1 = Wb[buf][kq * 4 + 1][tid];
            float w2 = Wb[buf][kq * 4 + 2][tid];
            float w3 = Wb[buf][kq * 4 + 3][tid];
            #pragma unroll
            for (int r = 0; r < 4; r++) {
                float4 xv = X4[r * 64 + c * 4 + kq];
                float a = acc[r];
                a = fmaf(xv.x, w0, a);
                a = fmaf(xv.y, w1, a);
                a = fmaf(xv.z, w2, a);
                a = fmaf(xv.w, w3, a);
                acc[r] = a;
            }
        }
        __syncthreads();
        if (c + 2 < 16) pref(c + 2, buf);
    }

    #pragma unroll
    for (int r = 0; r < 4; r++)
        Ys[r][tid] = acc[r];
    __syncthreads();

    // Per-row inverse L2 norm: warp w (0..3) reduces row w
    const int warp = tid >> 5, lane = tid & 31;
    if (warp < 4) {
        float s = 0.f;
        #pragma unroll
        for (int k = lane; k < 256; k += 32) {
            float v = Ys[warp][k];
            s += v * v;
        }
        #pragma unroll
        for (int o = 16; o > 0; o >>= 1)
            s += __shfl_xor_sync(0xFFFFFFFFu, s, o);
        if (lane == 0)
            inv4[warp] = rsqrtf(fmaxf(s, 1e-12f));
    }
    __syncthreads();

    // Pred head [256 -> 50]; normalization folded as output scale.
    const int c  = tid & 63;
    const int rg = tid >> 6;
    if (c < 50) {
        float a = 0.f;
        #pragma unroll 16
        for (int k = 0; k < 256; k++)
            a = fmaf(Ys[rg][k], __ldg(wp + (size_t)k * 50 + c), a);
        out[(size_t)(r0 + rg) * 50 + c] = a * inv4[rg];
    }
}

// ---------------------------------------------------------------------------
extern "C" void kernel_launch(void* const* d_in, const int* in_sizes, int n_in,
                              void* d_out, int out_size)
{
    const float* features = (const float*)d_in[0];
    const int*   adj      = (const int*)d_in[1];
    const int*   batch    = (const int*)d_in[2];   // int32 (JAX x64 disabled)
    const float* ws0      = (const float*)d_in[3];
    const float* wn0      = (const float*)d_in[4];
    const float* ws1      = (const float*)d_in[5];
    const float* wn1      = (const float*)d_in[6];
    const float* wp       = (const float*)d_in[7];
    float*       out      = (float*)d_out;

    k_layer0<<<NTOT / RT, 256>>>(features, adj, batch, ws0, wn0);
    k_tail<<<BATCH / 4, 256>>>(ws1, wn1, wp, out);
}

// round 13
// speedup vs baseline: 1.5507x; 1.2844x over previous
#include <cuda_runtime.h>
#include <cstddef>
#include <cstdint>

// Problem constants (fixed by setup_inputs)
#define BATCH 1024
#define F1 10          // layer-1 fanout
#define F0 25          // layer-0 fanout
#define D 128          // feature dim
#define NROWS1 (BATCH*F1)        // 10240
#define NTOT (BATCH + NROWS1)    // 11264
#define RT 32                    // rows per layer-0 block (NTOT/RT = 352)

typedef unsigned long long u64;

// Scratch (device globals — no allocations allowed).
__device__ float  g_N[(size_t)NTOT * 256];
__device__ float2 g_W0i[128 * 128];   // (ws0, wn0) interleaved, [k][c]
__device__ float2 g_W1i[256 * 128];   // (ws1, wn1) interleaved, [k][c]

// f32x2 packed-FMA helpers (Blackwell FFMA2: two independent rn-rounded fp32
// FMAs per instruction -> halves the FFMA issue count, bit-identical results)
#define FMA2(d, a, b, c_) \
    asm("fma.rn.f32x2 %0, %1, %2, %3;" : "=l"(d) : "l"(a), "l"(b), "l"(c_))
#define UNPACK2(lo, hi, v) \
    asm("mov.b64 {%0, %1}, %2;" : "=f"(lo), "=f"(hi) : "l"(v))

// ---------------------------------------------------------------------------
// K0: build interleaved weight tables (deterministic, graph-capturable).
// 49152 elements total: 16384 for layer0, 32768 for layer1.
// ---------------------------------------------------------------------------
__global__ void k_prep(const float* __restrict__ ws0, const float* __restrict__ wn0,
                       const float* __restrict__ ws1, const float* __restrict__ wn1)
{
    int i = blockIdx.x * 256 + threadIdx.x;
    if (i < 16384) {
        g_W0i[i] = make_float2(ws0[i], wn0[i]);
    } else {
        int j = i - 16384;
        g_W1i[j] = make_float2(ws1[j], wn1[j]);
    }
}

// ---------------------------------------------------------------------------
// Gather: warp-cooperative. Warp w produces rows w, w+8, w+16, w+24; for each
// row it loads the self feature row and accumulates the neighbor mean, then
// writes them INTERLEAVED as float2 (self, nmean) per k -> ready for f32x2.
// CNT compile-time -> fully unrolled -> high MLP.
// ---------------------------------------------------------------------------
template<int CNT, bool LVL0>
__device__ __forceinline__ void gather_rows(
    const float* __restrict__ features, const int* __restrict__ adj,
    const int* __restrict__ batch, int r0,
    float2 (*Xi)[D], int warp, int lane)
{
    #pragma unroll
    for (int rr = warp; rr < RT; rr += 8) {
        int r = r0 + rr;
        int s;
        if (LVL0) {
            s = __ldg(batch + r);
        } else {
            int i = r - BATCH;
            s = __ldg(adj + (size_t)__ldg(batch + i / F1) * 128 + (i % F1));
        }
        float4 sv = ((const float4*)(features + (size_t)s * D))[lane];

        const int* arow = adj + (size_t)s * 128;
        float4 acc = make_float4(0.f, 0.f, 0.f, 0.f);
        #pragma unroll
        for (int j = 0; j < CNT; j++) {
            int nb = __ldg(arow + j);
            float4 nv = ((const float4*)(features + (size_t)nb * D))[lane];
            acc.x += nv.x; acc.y += nv.y; acc.z += nv.z; acc.w += nv.w;
        }
        const float inv = 1.f / CNT;
        acc.x *= inv; acc.y *= inv; acc.z *= inv; acc.w *= inv;

        float4* dst = (float4*)&Xi[rr][4 * lane];
        dst[0] = make_float4(sv.x, acc.x, sv.y, acc.y);
        dst[1] = make_float4(sv.z, acc.z, sv.w, acc.w);
    }
}

// ---------------------------------------------------------------------------
// K_A: fused sample + aggregate + layer-0 GEMM (+ReLU), f32x2 packed.
// grid = 352 x 256 thr; block = 32 rows x 256 output cols.
// Thread owns paired columns (c, c+128) for 16 rows (tid>>7 selects row half).
// Weights streamed per-thread from interleaved table with register
// double-buffer; no barriers inside the k-loop.
// ---------------------------------------------------------------------------
__global__ void __launch_bounds__(256)
k_layer0(const float* __restrict__ features, const int* __restrict__ adj,
         const int* __restrict__ batch)
{
    __shared__ float2 Xi[RT][D];       // 32 KB interleaved (self, nmean)

    const int tid  = threadIdx.x;
    const int warp = tid >> 5, lane = tid & 31;
    const int r0   = blockIdx.x * RT;

    if (r0 < BATCH)
        gather_rows<F1, true >(features, adj, batch, r0, Xi, warp, lane);
    else
        gather_rows<F0, false>(features, adj, batch, r0, Xi, warp, lane);
    __syncthreads();

    const int c    = tid & 127;
    const int half = tid >> 7;          // 0: rows 0-15, 1: rows 16-31

    const u64* X = (const u64*)&Xi[half * 16][0];       // 16 rows x 128 k
    const u64* W = ((const u64*)g_W0i) + c;             // stride 128 per k

    u64 acc[16];
    #pragma unroll
    for (int r = 0; r < 16; r++) acc[r] = 0ull;

    u64 w2[2][8];
    #pragma unroll
    for (int j = 0; j < 8; j++)
        w2[0][j] = __ldg(W + (size_t)j * 128);

    #pragma unroll
    for (int g = 0; g < 16; g++) {
        const int cur = g & 1, nxt = cur ^ 1;
        if (g < 15) {
            #pragma unroll
            for (int j = 0; j < 8; j++)
                w2[nxt][j] = __ldg(W + (size_t)((g + 1) * 8 + j) * 128);
        }
        #pragma unroll
        for (int j = 0; j < 8; j++) {
            const int k = g * 8 + j;
            #pragma unroll
            for (int r = 0; r < 16; r++) {
                u64 x = X[r * D + k];                  // broadcast LDS.64
                FMA2(acc[r], x, w2[cur][j], acc[r]);
            }
        }
    }

    #pragma unroll
    for (int r = 0; r < 16; r++) {
        float lo, hi;
        UNPACK2(lo, hi, acc[r]);
        const size_t R = (size_t)(r0 + half * 16 + r);
        g_N[R * 256 + c]       = fmaxf(lo, 0.f);
        g_N[R * 256 + c + 128] = fmaxf(hi, 0.f);
    }
}

// ---------------------------------------------------------------------------
// K_B: fused tail: mean-of-10 + layer-1 GEMM (f32x2) + l2-normalize + pred.
// grid = 128 x 256 thr; 8 batch rows per block; warp w builds row w of the
// interleaved (n0, m1) tile. Ys aliases Ni after the GEMM.
// ---------------------------------------------------------------------------
__global__ void __launch_bounds__(256)
k_tail(const float* __restrict__ wp, float* __restrict__ out)
{
    __shared__ float2 Ni[8][256];      // 16 KB interleaved (n0, m1)
    __shared__ float  inv8[8];

    const int tid  = threadIdx.x;
    const int warp = tid >> 5, lane = tid & 31;
    const int r0   = blockIdx.x * 8;

    // Phase 1: one row per warp. lane covers k = 8*lane .. 8*lane+7.
    {
        const int R = r0 + warp;
        const float4* n0p = (const float4*)(g_N + (size_t)R * 256);
        float4 a0 = n0p[2 * lane], a1 = n0p[2 * lane + 1];

        const float* mb = g_N + (size_t)(BATCH + R * F1) * 256;
        float4 b0 = make_float4(0.f, 0.f, 0.f, 0.f);
        float4 b1 = make_float4(0.f, 0.f, 0.f, 0.f);
        #pragma unroll
        for (int j = 0; j < F1; j++) {
            const float4* mp = (const float4*)(mb + (size_t)j * 256);
            float4 t0 = mp[2 * lane], t1 = mp[2 * lane + 1];
            b0.x += t0.x; b0.y += t0.y; b0.z += t0.z; b0.w += t0.w;
            b1.x += t1.x; b1.y += t1.y; b1.z += t1.z; b1.w += t1.w;
        }
        const float inv = 1.f / F1;
        b0.x *= inv; b0.y *= inv; b0.z *= inv; b0.w *= inv;
        b1.x *= inv; b1.y *= inv; b1.z *= inv; b1.w *= inv;

        float4* dst = (float4*)&Ni[warp][8 * lane];
        dst[0] = make_float4(a0.x, b0.x, a0.y, b0.y);
        dst[1] = make_float4(a0.z, b0.z, a0.w, b0.w);
        dst[2] = make_float4(a1.x, b1.x, a1.y, b1.y);
        dst[3] = make_float4(a1.z, b1.z, a1.w, b1.w);
    }
    __syncthreads();

    // Phase 2: GEMM K=256. Thread owns paired cols (c, c+128) for 4 rows.
    const int c    = tid & 127;
    const int half = tid >> 7;          // rows 0-3 or 4-7

    const u64* X = (const u64*)&Ni[half * 4][0];
    const u64* W = ((const u64*)g_W1i) + c;

    u64 acc[4] = {0ull, 0ull, 0ull, 0ull};
    u64 w2[2][8];
    #pragma unroll
    for (int j = 0; j < 8; j++)
        w2[0][j] = __ldg(W + (size_t)j * 128);

    #pragma unroll
    for (int g = 0; g < 32; g++) {
        const int cur = g & 1, nxt = cur ^ 1;
        if (g < 31) {
            #pragma unroll
            for (int j = 0; j < 8; j++)
                w2[nxt][j] = __ldg(W + (size_t)((g + 1) * 8 + j) * 128);
        }
        #pragma unroll
        for (int j = 0; j < 8; j++) {
            const int k = g * 8 + j;
            #pragma unroll
            for (int r = 0; r < 4; r++) {
                u64 x = X[r * 256 + k];
                FMA2(acc[r], x, w2[cur][j], acc[r]);
            }
        }
    }
    __syncthreads();                    // all Ni reads done -> safe to alias

    float* Ys = (float*)Ni;             // [8][256]
    #pragma unroll
    for (int r = 0; r < 4; r++) {
        float lo, hi;
        UNPACK2(lo, hi, acc[r]);
        const int rr = half * 4 + r;
        Ys[rr * 256 + c]       = lo;
        Ys[rr * 256 + c + 128] = hi;
    }
    __syncthreads();

    // Phase 3: per-row inverse L2 norm (warp w reduces row w)
    {
        float s = 0.f;
        #pragma unroll
        for (int k = lane; k < 256; k += 32) {
            float v = Ys[warp * 256 + k];
            s += v * v;
        }
        #pragma unroll
        for (int o = 16; o > 0; o >>= 1)
            s += __shfl_xor_sync(0xFFFFFFFFu, s, o);
        if (lane == 0)
            inv8[warp] = rsqrtf(fmaxf(s, 1e-12f));
    }
    __syncthreads();

    // Phase 4: pred head [256 -> 50]; normalization folded as output scale.
    const int cc = tid & 63;
    const int rg = tid >> 6;            // 4 groups x 2 rows
    if (cc < 50) {
        const int rl = rg * 2;
        float a0 = 0.f, a1 = 0.f;
        #pragma unroll 16
        for (int k = 0; k < 256; k++) {
            float w = __ldg(wp + (size_t)k * 50 + cc);
            a0 = fmaf(Ys[rl * 256 + k], w, a0);
            a1 = fmaf(Ys[(rl + 1) * 256 + k], w, a1);
        }
        out[(size_t)(r0 + rl) * 50 + cc]     = a0 * inv8[rl];
        out[(size_t)(r0 + rl + 1) * 50 + cc] = a1 * inv8[rl + 1];
    }
}

// ---------------------------------------------------------------------------
extern "C" void kernel_launch(void* const* d_in, const int* in_sizes, int n_in,
                              void* d_out, int out_size)
{
    const float* features = (const float*)d_in[0];
    const int*   adj      = (const int*)d_in[1];
    const int*   batch    = (const int*)d_in[2];   // int32 (JAX x64 disabled)
    const float* ws0      = (const float*)d_in[3];
    const float* wn0      = (const float*)d_in[4];
    const float* ws1      = (const float*)d_in[5];
    const float* wn1      = (const float*)d_in[6];
    const float* wp       = (const float*)d_in[7];
    float*       out      = (float*)d_out;

    k_prep<<<192, 256>>>(ws0, wn0, ws1, wn1);
    k_layer0<<<NTOT / RT, 256>>>(features, adj, batch);
    k_tail<<<BATCH / 8, 256>>>(wp, out);
}